// round 4
// baseline (speedup 1.0000x reference)
#include <cuda_runtime.h>
#include <math.h>

#define IMG   512
#define NB    4
#define NP    512
#define RCAP  37
#define PLANE (IMG * IMG)
#define GRID  512
#define TPB   256

// 32 NN partials (max over 64 points of min NN d^2), still squared
__device__ float g_part[32];
// grid-barrier counter: grows by GRID per launch/replay; epoch = floor(val/GRID)
__device__ int   g_bar;

__global__ void __launch_bounds__(TPB, 4)
fused_kernel(const float* __restrict__ cp,
             const float* __restrict__ alpha,
             float* __restrict__ out)
{
    const int blk = blockIdx.x;
    const int t   = threadIdx.x;

    __shared__ float2 pts[NP];
    __shared__ float  red[64];
    __shared__ float  s_r[NB];
    __shared__ float  s_rall;

    // ---------------- phase 1a: zero my 16KB slice of the output --------------
    {
        float4* o4 = (float4*)out;                 // 524288 float4 total
        const float4 z = make_float4(0.f, 0.f, 0.f, 0.f);
        const int base = blk * 1024 + t;
        o4[base] = z; o4[base + 256] = z; o4[base + 512] = z; o4[base + 768] = z;
    }

    // ---------------- phase 1b: NN partials (blocks 0..31) --------------------
    if (blk < 32) {
        const int batch = blk >> 3;
        const int seg   = blk & 7;
        pts[t]       = ((const float2*)cp)[batch * NP + t];
        pts[t + 256] = ((const float2*)cp)[batch * NP + t + 256];
        __syncthreads();

        const int i   = seg * 64 + (t >> 2);   // point handled by this group
        const int sub = t & 3;                 // 4 threads/point, 128 j's each
        const float2 me = pts[i];

        float mind2 = 3.0e38f;
        const int j0 = sub * 128;
#pragma unroll 8
        for (int j = j0; j < j0 + 128; ++j) {
            float dx = me.x - pts[j].x;
            float dy = me.y - pts[j].y;
            float d2 = fmaf(dy, dy, dx * dx);
            if (j != i) mind2 = fminf(mind2, d2);
        }
        mind2 = fminf(mind2, __shfl_down_sync(0xffffffffu, mind2, 2, 4));
        mind2 = fminf(mind2, __shfl_down_sync(0xffffffffu, mind2, 1, 4));
        if (sub == 0) red[t >> 2] = mind2;
        __syncthreads();

        if (t < 32) {
            float v = fmaxf(red[t], red[t + 32]);
#pragma unroll
            for (int o = 16; o > 0; o >>= 1)
                v = fmaxf(v, __shfl_down_sync(0xffffffffu, v, o));
            if (t == 0) g_part[blk] = v;
        }
    }

    // ---------------- grid-wide barrier (replay-safe epoch) -------------------
    if (t == 0) {
        __threadfence();                              // publish zeros + partials
        const int base   = atomicAdd(&g_bar, 1);      // old value
        const int target = (base / GRID + 1) * GRID;  // end of this launch's epoch
        while (*((volatile int*)&g_bar) < target) { }
        __threadfence();
    }
    __syncthreads();

    // ---------------- fold partials once per block ----------------------------
    if (t < 32) {
        const float v = g_part[t];
        float a = v;                                   // global max (for rmax)
#pragma unroll
        for (int o = 16; o > 0; o >>= 1)
            a = fmaxf(a, __shfl_down_sync(0xffffffffu, a, o));
        float w = v;                                   // per-batch max (8 lanes)
        w = fmaxf(w, __shfl_down_sync(0xffffffffu, w, 4, 8));
        w = fmaxf(w, __shfl_down_sync(0xffffffffu, w, 2, 8));
        w = fmaxf(w, __shfl_down_sync(0xffffffffu, w, 1, 8));
        if ((t & 7) == 0) s_r[t >> 3] = 2.0f * sqrtf(w);
        if (t == 0)       s_rall      = 2.0f * sqrtf(a);
    }
    __syncthreads();

    // ---------------- phase 2: splat point #blk of each batch -----------------
    const int rmax = (int)fminf(ceilf(s_rall), (float)RCAP);
    const int W2   = 2 * rmax;
    const int lane = t & 31;
    const int wid  = t >> 5;

    const int  nch   = (W2 + 31) >> 5;
    const int  ncf   = nch - 1;
    const bool plast = ((ncf << 5) + lane) < W2;
    const float lo = (float)rmax, hi = (float)(IMG - rmax);

#pragma unroll
    for (int k = 0; k < NB; ++k) {
        const int   pid   = k * NP + blk;
        const float inv_r = 1.0f / s_r[k];
        const float2 c = ((const float2*)cp)[pid];
        const float2 a = ((const float2*)alpha)[pid];

        const int bx = (int)floorf(fminf(fmaxf(c.x, lo), hi)) - rmax;
        const int by = (int)floorf(fminf(fmaxf(c.y, lo), hi)) - rmax;

        float* __restrict__ o0 = out + (size_t)k * 2 * PLANE;

        const float sx0  = ((float)(bx + lane) - c.x) * inv_r;
        const float dsx  = 32.0f * inv_r;
        float       sy   = ((float)(by + wid) - c.y) * inv_r;
        const float dsy8 = 8.0f * inv_r;

        int rowoff = (by + wid) * IMG + bx + lane;

        for (int iy = wid; iy < W2; iy += 8, sy += dsy8, rowoff += 8 * IMG) {
            const float sy2 = sy * sy;
            float sx  = sx0;
            int   off = rowoff;

            for (int cdx = 0; cdx < ncf; ++cdx, sx += dsx, off += 32) {
                const float d2 = fmaf(sx, sx, sy2);
                float dist;
                asm("sqrt.approx.f32 %0, %1;" : "=f"(dist) : "f"(d2));
                const float om  = 1.0f - dist;
                const float om2 = om * om;
                const float w   = (om2 * om2) * fmaf(4.0f, dist, 1.0f);
                if (dist < 1.0f) {
                    atomicAdd(o0 + off,         w * a.x);
                    atomicAdd(o0 + off + PLANE, w * a.y);
                }
            }
            {   // peeled last chunk, hoisted lane mask
                const float d2 = fmaf(sx, sx, sy2);
                float dist;
                asm("sqrt.approx.f32 %0, %1;" : "=f"(dist) : "f"(d2));
                const float om  = 1.0f - dist;
                const float om2 = om * om;
                const float w   = (om2 * om2) * fmaf(4.0f, dist, 1.0f);
                if (plast && dist < 1.0f) {
                    atomicAdd(o0 + off,         w * a.x);
                    atomicAdd(o0 + off + PLANE, w * a.y);
                }
            }
        }
    }
}

// ---------------------------------------------------------------------------
extern "C" void kernel_launch(void* const* d_in, const int* in_sizes, int n_in,
                              void* d_out, int out_size) {
    const float* cpoint = (const float*)d_in[0];  // [4,512,2]
    const float* alpha  = (const float*)d_in[1];  // [4,512,2]
    float* out = (float*)d_out;                   // [4,2,512,512]
    (void)in_sizes; (void)n_in; (void)out_size;

    fused_kernel<<<GRID, TPB>>>(cpoint, alpha, out);
}

// round 5
// speedup vs baseline: 1.6115x; 1.6115x over previous
#include <cuda_runtime.h>
#include <math.h>

#define IMG    512
#define NB     4
#define NP     512
#define RCAP   37
#define PLANE  (IMG * IMG)
#define TILE_W 32
#define TILE_H 8
#define TPB    256     // one thread per pixel of the tile

// 32 NN partials: g_part[batch*8 + seg] = max over 64 points of min-NN d^2
__device__ float g_part[32];

// ---------------------------------------------------------------------------
// Kernel 1: NN partials. 32 blocks (8/batch), 512 threads, 4 threads/point.
// ---------------------------------------------------------------------------
__global__ void __launch_bounds__(512)
nn_kernel(const float* __restrict__ cp) {
    const int blk = blockIdx.x;      // 0..31
    const int t   = threadIdx.x;
    const int batch = blk >> 3;
    const int seg   = blk & 7;

    __shared__ float2 pts[NP];
    __shared__ float  red[64];

    pts[t] = ((const float2*)cp)[batch * NP + t];
    __syncthreads();

    const int i   = seg * 64 + (t >> 3);  // 8 threads per point
    const int sub = t & 7;                // each scans 64 j's
    const float2 me = pts[i];

    float mind2 = 3.0e38f;
    const int j0 = sub * 64;
#pragma unroll 8
    for (int j = j0; j < j0 + 64; ++j) {
        float dx = me.x - pts[j].x;
        float dy = me.y - pts[j].y;
        float d2 = fmaf(dy, dy, dx * dx);
        if (j != i) mind2 = fminf(mind2, d2);
    }
#pragma unroll
    for (int o = 4; o > 0; o >>= 1)
        mind2 = fminf(mind2, __shfl_down_sync(0xffffffffu, mind2, o, 8));
    if (sub == 0) red[t >> 3] = mind2;
    __syncthreads();

    if (t < 32) {
        float v = fmaxf(red[t], red[t + 32]);
#pragma unroll
        for (int o = 16; o > 0; o >>= 1)
            v = fmaxf(v, __shfl_down_sync(0xffffffffu, v, o));
        if (t == 0) g_part[blk] = v;   // squared
    }
}

// ---------------------------------------------------------------------------
// Kernel 2: gather. One block per (batch, 32x8 pixel tile). 4096 blocks.
//   preamble: fold partials -> r_b, rmax; prefilter batch's 512 points whose
//   splat box intersects this tile; ballot-compact (point order, deterministic).
//   main: each thread = one pixel; sum Wendland contributions from candidates.
// ---------------------------------------------------------------------------
__global__ void __launch_bounds__(TPB)
gather_kernel(const float* __restrict__ cp,
              const float* __restrict__ alpha,
              float* __restrict__ out) {
    const int bid  = blockIdx.x;
    const int b    = bid >> 10;              // 1024 tiles per batch
    const int tile = bid & 1023;
    const int x0   = (tile & 15) << 5;       // 16 x-tiles * 32
    const int y0   = (tile >> 4) << 3;       // 64 y-tiles * 8
    const int t    = threadIdx.x;
    const int lane = t & 31;
    const int wid  = t >> 5;

    __shared__ float4 sPt[NP];   // cx*inv_r, cy*inv_r, ax, ay
    __shared__ float2 sBc[NP];   // box centers (exact half-integers)
    __shared__ float  s_invr, s_rmaxf;
    __shared__ int    s_wcnt[8], s_wbase[8], s_total;

    // -- fold the 32 NN partials (warp 0) --
    if (t < 32) {
        float v = g_part[t];
        float g8 = v;                             // per-batch (8-lane group) max
        g8 = fmaxf(g8, __shfl_xor_sync(0xffffffffu, g8, 4));
        g8 = fmaxf(g8, __shfl_xor_sync(0xffffffffu, g8, 2));
        g8 = fmaxf(g8, __shfl_xor_sync(0xffffffffu, g8, 1));
        float ga = g8;                            // global max
        ga = fmaxf(ga, __shfl_xor_sync(0xffffffffu, ga, 8));
        ga = fmaxf(ga, __shfl_xor_sync(0xffffffffu, ga, 16));
        const float own = __shfl_sync(0xffffffffu, g8, b * 8);
        if (t == 0) {
            const float r    = 2.0f * sqrtf(own);
            const float rall = 2.0f * sqrtf(ga);
            s_rmaxf = fminf(ceilf(rall), (float)RCAP);
            s_invr  = 1.0f / r;
            s_total = 0;
        }
    }
    __syncthreads();

    const float rmaxf = s_rmaxf;
    const float inv_r = s_invr;
    const float lo = rmaxf, hi = (float)IMG - rmaxf;
    const float W2m1 = 2.0f * rmaxf - 1.0f;
    const float xlo = (float)x0 - W2m1, xhi = (float)(x0 + TILE_W - 1);
    const float ylo = (float)y0 - W2m1, yhi = (float)(y0 + TILE_H - 1);

    // -- prefilter + ordered compaction, two rounds (points t and t+256) --
#pragma unroll
    for (int rnd = 0; rnd < 2; ++rnd) {
        const int p = t + rnd * 256;
        const float2 c = ((const float2*)cp)[b * NP + p];
        const float bx = floorf(fminf(fmaxf(c.x, lo), hi)) - rmaxf;  // exact int
        const float by = floorf(fminf(fmaxf(c.y, lo), hi)) - rmaxf;
        const bool keep = (bx >= xlo) & (bx <= xhi) & (by >= ylo) & (by <= yhi);

        const unsigned m = __ballot_sync(0xffffffffu, keep);
        if (lane == 0) s_wcnt[wid] = __popc(m);
        __syncthreads();
        if (t == 0) {
            int run = s_total;
#pragma unroll
            for (int w = 0; w < 8; ++w) { s_wbase[w] = run; run += s_wcnt[w]; }
            s_total = run;
        }
        __syncthreads();
        if (keep) {
            const int idx = s_wbase[wid] + __popc(m & ((1u << lane) - 1u));
            const float2 a = ((const float2*)alpha)[b * NP + p];
            sPt[idx] = make_float4(c.x * inv_r, c.y * inv_r, a.x, a.y);
            sBc[idx] = make_float2(bx + rmaxf - 0.5f, by + rmaxf - 0.5f);
        }
        __syncthreads();
    }

    // -- per-pixel accumulation --
    const int K = s_total;
    const float pxf = (float)(x0 + lane);
    const float pyf = (float)(y0 + wid);
    const float pxs = pxf * inv_r;
    const float pys = pyf * inv_r;
    const float hw  = rmaxf - 0.5f;

    float accx = 0.f, accy = 0.f;
#pragma unroll 4
    for (int k = 0; k < K; ++k) {
        const float4 P  = sPt[k];
        const float2 Bc = sBc[k];
        const float dxs = pxs - P.x;
        const float dys = pys - P.y;
        const float d2  = fmaf(dxs, dxs, dys * dys);
        float dist;
        asm("sqrt.approx.f32 %0, %1;" : "=f"(dist) : "f"(d2));
        const float om  = 1.0f - dist;
        const float om2 = om * om;
        const float w   = (om2 * om2) * fmaf(4.0f, dist, 1.0f);
        // exact box test (all half-integers) + dist<1 (boundary weight ~0)
        const bool live = (fabsf(pxf - Bc.x) <= hw) &
                          (fabsf(pyf - Bc.y) <= hw) & (d2 < 1.0f);
        if (live) {
            accx = fmaf(w, P.z, accx);
            accy = fmaf(w, P.w, accy);
        }
    }

    const size_t base = (size_t)b * 2 * PLANE + (size_t)(y0 + wid) * IMG + x0 + lane;
    out[base]         = accx;
    out[base + PLANE] = accy;
}

// ---------------------------------------------------------------------------
extern "C" void kernel_launch(void* const* d_in, const int* in_sizes, int n_in,
                              void* d_out, int out_size) {
    const float* cpoint = (const float*)d_in[0];  // [4,512,2]
    const float* alpha  = (const float*)d_in[1];  // [4,512,2]
    float* out = (float*)d_out;                   // [4,2,512,512]
    (void)in_sizes; (void)n_in; (void)out_size;

    nn_kernel<<<32, 512>>>(cpoint);
    gather_kernel<<<NB * 1024, TPB>>>(cpoint, alpha, out);
}

// round 6
// speedup vs baseline: 1.8237x; 1.1317x over previous
#include <cuda_runtime.h>
#include <math.h>

#define IMG   512
#define NB    4
#define NP    512
#define RCAP  37
#define PLANE (IMG * IMG)
#define TW    32
#define TH    16
#define TPB   128           // 32 lanes x 4 warps; each thread covers 4 rows

// 32 NN partials: g_part[batch*8 + seg] = max over 64 points of min-NN d^2
__device__ float g_part[32];

// ---------------------------------------------------------------------------
// Kernel 1: NN partials. 32 blocks (8/batch), 512 threads, 8 threads/point.
// ---------------------------------------------------------------------------
__global__ void __launch_bounds__(512)
nn_kernel(const float* __restrict__ cp) {
    const int blk = blockIdx.x;
    const int t   = threadIdx.x;
    const int batch = blk >> 3;
    const int seg   = blk & 7;

    __shared__ float2 pts[NP];
    __shared__ float  red[64];

    pts[t] = ((const float2*)cp)[batch * NP + t];
    __syncthreads();

    const int i   = seg * 64 + (t >> 3);
    const int sub = t & 7;
    const float2 me = pts[i];

    float mind2 = 3.0e38f;
    const int j0 = sub * 64;
#pragma unroll 8
    for (int j = j0; j < j0 + 64; ++j) {
        float dx = me.x - pts[j].x;
        float dy = me.y - pts[j].y;
        float d2 = fmaf(dy, dy, dx * dx);
        if (j != i) mind2 = fminf(mind2, d2);
    }
#pragma unroll
    for (int o = 4; o > 0; o >>= 1)
        mind2 = fminf(mind2, __shfl_down_sync(0xffffffffu, mind2, o, 8));
    if (sub == 0) red[t >> 3] = mind2;
    __syncthreads();

    if (t < 32) {
        float v = fmaxf(red[t], red[t + 32]);
#pragma unroll
        for (int o = 16; o > 0; o >>= 1)
            v = fmaxf(v, __shfl_down_sync(0xffffffffu, v, o));
        if (t == 0) g_part[blk] = v;   // squared
    }
}

// ---------------------------------------------------------------------------
// Kernel 2: gather. One block per (batch, 32x16 tile). 2048 blocks, TPB=128.
// Thread (lane, wid) owns pixels (x0+lane, y0+wid+4r), r=0..3.
// ---------------------------------------------------------------------------
__global__ void __launch_bounds__(TPB, 12)
gather_kernel(const float* __restrict__ cp,
              const float* __restrict__ alpha,
              float* __restrict__ out) {
    const int bid  = blockIdx.x;
    const int b    = bid >> 9;               // 512 tiles per batch
    const int tile = bid & 511;
    const int x0   = (tile & 15) << 5;       // 16 x-tiles * 32
    const int y0   = (tile >> 4) << 4;       // 32 y-tiles * 16
    const int t    = threadIdx.x;
    const int lane = t & 31;
    const int wid  = t >> 5;                 // 0..3

    __shared__ float4 sPt[NP];   // cx/r, cy/r, ax, ay
    __shared__ float2 sBc[NP];   // box center (half-integers)
    __shared__ float  s_invr, s_rmaxf;
    __shared__ int    s_wcnt[4], s_wbase[4], s_total;

    // ---- fold the 32 NN partials (warp 0) ----
    if (t < 32) {
        float v = g_part[t];
        float g8 = v;
        g8 = fmaxf(g8, __shfl_xor_sync(0xffffffffu, g8, 4));
        g8 = fmaxf(g8, __shfl_xor_sync(0xffffffffu, g8, 2));
        g8 = fmaxf(g8, __shfl_xor_sync(0xffffffffu, g8, 1));
        float ga = g8;
        ga = fmaxf(ga, __shfl_xor_sync(0xffffffffu, ga, 8));
        ga = fmaxf(ga, __shfl_xor_sync(0xffffffffu, ga, 16));
        const float own = __shfl_sync(0xffffffffu, g8, b * 8);
        if (t == 0) {
            const float r    = 2.0f * sqrtf(own);
            const float rall = 2.0f * sqrtf(ga);
            s_rmaxf = fminf(ceilf(rall), (float)RCAP);
            s_invr  = 1.0f / r;
            s_total = 0;
        }
    }
    __syncthreads();

    const float rmaxf = s_rmaxf;
    const float inv_r = s_invr;
    const float lo = rmaxf, hi = (float)IMG - rmaxf;
    const float W2m1 = 2.0f * rmaxf - 1.0f;
    const float xlo = (float)x0 - W2m1, xhi = (float)(x0 + TW - 1);
    const float ylo = (float)y0 - W2m1, yhi = (float)(y0 + TH - 1);

    // ---- prefilter + ordered compaction: 4 rounds of 128 points ----
#pragma unroll
    for (int rnd = 0; rnd < 4; ++rnd) {
        const int p = t + rnd * TPB;
        const float2 c = ((const float2*)cp)[b * NP + p];
        const float bx = floorf(fminf(fmaxf(c.x, lo), hi)) - rmaxf;  // exact int
        const float by = floorf(fminf(fmaxf(c.y, lo), hi)) - rmaxf;
        const bool keep = (bx >= xlo) & (bx <= xhi) & (by >= ylo) & (by <= yhi);

        const unsigned m = __ballot_sync(0xffffffffu, keep);
        if (lane == 0) s_wcnt[wid] = __popc(m);
        __syncthreads();
        if (t == 0) {
            int run = s_total;
#pragma unroll
            for (int w = 0; w < 4; ++w) { s_wbase[w] = run; run += s_wcnt[w]; }
            s_total = run;
        }
        __syncthreads();
        if (keep) {
            const int idx = s_wbase[wid] + __popc(m & ((1u << lane) - 1u));
            const float2 a = ((const float2*)alpha)[b * NP + p];
            sPt[idx] = make_float4(c.x * inv_r, c.y * inv_r, a.x, a.y);
            sBc[idx] = make_float2(bx + rmaxf - 0.5f, by + rmaxf - 0.5f);
        }
    }
    __syncthreads();

    // ---- per-pixel accumulation: 4 rows per thread ----
    const int K = s_total;
    const float pxf  = (float)(x0 + lane);
    const float pyf0 = (float)(y0 + wid);
    const float pxs  = pxf * inv_r;
    const float pys0 = pyf0 * inv_r;
    const float d4s  = 4.0f * inv_r;
    const float hw   = rmaxf - 0.5f;

    float ax0 = 0.f, ay0 = 0.f, ax1 = 0.f, ay1 = 0.f;
    float ax2 = 0.f, ay2 = 0.f, ax3 = 0.f, ay3 = 0.f;

    for (int k = 0; k < K; ++k) {
        const float4 P  = sPt[k];
        const float2 Bc = sBc[k];
        const float dxs = pxs - P.x;
        const float dx2 = dxs * dxs;
        const float adx = fabsf(pxf - Bc.x);
        float dys = pys0 - P.y;
        float dyb = pyf0 - Bc.y;

#define ROW(AX, AY)                                                          \
        {                                                                    \
            const float d2 = fmaf(dys, dys, dx2);                            \
            float dist;                                                      \
            asm("sqrt.approx.f32 %0, %1;" : "=f"(dist) : "f"(d2));           \
            const float om  = __saturatef(1.0f - dist);                      \
            const float om2 = om * om;                                       \
            const float w   = (om2 * om2) * fmaf(4.0f, dist, 1.0f);          \
            if (fmaxf(adx, fabsf(dyb)) <= hw) {                              \
                AX = fmaf(w, P.z, AX);                                       \
                AY = fmaf(w, P.w, AY);                                       \
            }                                                                \
            dys += d4s;                                                      \
            dyb += 4.0f;                                                     \
        }
        ROW(ax0, ay0) ROW(ax1, ay1) ROW(ax2, ay2) ROW(ax3, ay3)
#undef ROW
    }

    // ---- write out (coalesced per warp) ----
    float* __restrict__ o0 = out + (size_t)b * 2 * PLANE;
    const int p0 = (y0 + wid) * IMG + x0 + lane;
    o0[p0]                 = ax0;  o0[p0 + PLANE]             = ay0;
    o0[p0 + 4 * IMG]       = ax1;  o0[p0 + 4 * IMG + PLANE]   = ay1;
    o0[p0 + 8 * IMG]       = ax2;  o0[p0 + 8 * IMG + PLANE]   = ay2;
    o0[p0 + 12 * IMG]      = ax3;  o0[p0 + 12 * IMG + PLANE]  = ay3;
}

// ---------------------------------------------------------------------------
extern "C" void kernel_launch(void* const* d_in, const int* in_sizes, int n_in,
                              void* d_out, int out_size) {
    const float* cpoint = (const float*)d_in[0];  // [4,512,2]
    const float* alpha  = (const float*)d_in[1];  // [4,512,2]
    float* out = (float*)d_out;                   // [4,2,512,512]
    (void)in_sizes; (void)n_in; (void)out_size;

    nn_kernel<<<32, 512>>>(cpoint);
    gather_kernel<<<NB * 512, TPB>>>(cpoint, alpha, out);
}

// round 7
// speedup vs baseline: 1.8397x; 1.0088x over previous
#include <cuda_runtime.h>
#include <math.h>

#define IMG   512
#define NB    4
#define NP    512
#define RCAP  37
#define PLANE (IMG * IMG)
#define TW    32
#define TH    16
#define TPB   128           // 32 lanes x 4 warps; each thread covers 4 rows

// 32 NN partials: g_part[batch*8 + seg] = max over 64 points of min-NN d^2
__device__ float g_part[32];

// ---------------------------------------------------------------------------
// Kernel 1: NN partials. 32 blocks (8/batch), 512 threads, 8 threads/point.
// ---------------------------------------------------------------------------
__global__ void __launch_bounds__(512)
nn_kernel(const float* __restrict__ cp) {
    const int blk = blockIdx.x;
    const int t   = threadIdx.x;
    const int batch = blk >> 3;
    const int seg   = blk & 7;

    __shared__ float2 pts[NP];
    __shared__ float  red[64];

    pts[t] = ((const float2*)cp)[batch * NP + t];
    __syncthreads();

    const int i   = seg * 64 + (t >> 3);
    const int sub = t & 7;
    const float2 me = pts[i];

    float mind2 = 3.0e38f;
    const int j0 = sub * 64;
#pragma unroll 8
    for (int j = j0; j < j0 + 64; ++j) {
        float dx = me.x - pts[j].x;
        float dy = me.y - pts[j].y;
        float d2 = fmaf(dy, dy, dx * dx);
        if (j != i) mind2 = fminf(mind2, d2);
    }
#pragma unroll
    for (int o = 4; o > 0; o >>= 1)
        mind2 = fminf(mind2, __shfl_down_sync(0xffffffffu, mind2, o, 8));
    if (sub == 0) red[t >> 3] = mind2;
    __syncthreads();

    if (t < 32) {
        float v = fmaxf(red[t], red[t + 32]);
#pragma unroll
        for (int o = 16; o > 0; o >>= 1)
            v = fmaxf(v, __shfl_down_sync(0xffffffffu, v, o));
        if (t == 0) g_part[blk] = v;   // squared
    }
}

// ---------------------------------------------------------------------------
// Kernel 2: gather. One block per (batch, 32x16 tile). 2048 blocks, TPB=128.
// Thread (lane, wid) owns pixels (x0+lane, y0+wid+4r), r=0..3.
// ---------------------------------------------------------------------------
__global__ void __launch_bounds__(TPB, 16)
gather_kernel(const float* __restrict__ cp,
              const float* __restrict__ alpha,
              float* __restrict__ out) {
    const int bid  = blockIdx.x;
    const int b    = bid >> 9;               // 512 tiles per batch
    const int tile = bid & 511;
    const int x0   = (tile & 15) << 5;       // 16 x-tiles * 32
    const int y0   = (tile >> 4) << 4;       // 32 y-tiles * 16
    const int t    = threadIdx.x;
    const int lane = t & 31;
    const int wid  = t >> 5;                 // 0..3

    __shared__ float4 sPt[NP];   // cx/r, cy/r, ax, ay
    __shared__ float2 sBc[NP];   // box center (half-integers)
    __shared__ float  s_invr, s_rmaxf;
    __shared__ int    s_cnt[16], s_base[16];

    // ---- fold the 32 NN partials (warp 0) ----
    if (t < 32) {
        float v = g_part[t];
        float g8 = v;
        g8 = fmaxf(g8, __shfl_xor_sync(0xffffffffu, g8, 4));
        g8 = fmaxf(g8, __shfl_xor_sync(0xffffffffu, g8, 2));
        g8 = fmaxf(g8, __shfl_xor_sync(0xffffffffu, g8, 1));
        float ga = g8;
        ga = fmaxf(ga, __shfl_xor_sync(0xffffffffu, ga, 8));
        ga = fmaxf(ga, __shfl_xor_sync(0xffffffffu, ga, 16));
        const float own = __shfl_sync(0xffffffffu, g8, b * 8);
        if (t == 0) {
            const float r    = 2.0f * sqrtf(own);
            const float rall = 2.0f * sqrtf(ga);
            s_rmaxf = fminf(ceilf(rall), (float)RCAP);
            s_invr  = 1.0f / r;
        }
    }
    __syncthreads();

    const float rmaxf = s_rmaxf;
    const float inv_r = s_invr;
    const float lo = rmaxf, hi = (float)IMG - rmaxf;
    const float W2m1 = 2.0f * rmaxf - 1.0f;
    const float xlo = (float)x0 - W2m1, xhi = (float)(x0 + TW - 1);
    const float ylo = (float)y0 - W2m1, yhi = (float)(y0 + TH - 1);

    // ---- prefilter all 4 rounds, then one prefix + one scatter ----
    bool     keep[4];
    unsigned msk[4];
    float    kbx[4], kby[4];
#pragma unroll
    for (int rnd = 0; rnd < 4; ++rnd) {
        const int p = t + rnd * TPB;
        const float2 c = ((const float2*)cp)[b * NP + p];
        const float bx = floorf(fminf(fmaxf(c.x, lo), hi)) - rmaxf;  // exact int
        const float by = floorf(fminf(fmaxf(c.y, lo), hi)) - rmaxf;
        keep[rnd] = (bx >= xlo) & (bx <= xhi) & (by >= ylo) & (by <= yhi);
        kbx[rnd] = bx; kby[rnd] = by;
        msk[rnd] = __ballot_sync(0xffffffffu, keep[rnd]);
        if (lane == 0) s_cnt[rnd * 4 + wid] = __popc(msk[rnd]);
    }
    __syncthreads();
    if (t == 0) {
        int run = 0;
#pragma unroll
        for (int i = 0; i < 16; ++i) { s_base[i] = run; run += s_cnt[i]; }
        s_cnt[0] = run;   // reuse slot 0 as total
    }
    __syncthreads();
    const int K = s_cnt[0];
#pragma unroll
    for (int rnd = 0; rnd < 4; ++rnd) {
        if (keep[rnd]) {
            const int p   = t + rnd * TPB;
            const int idx = s_base[rnd * 4 + wid] +
                            __popc(msk[rnd] & ((1u << lane) - 1u));
            const float2 c = ((const float2*)cp)[b * NP + p];
            const float2 a = ((const float2*)alpha)[b * NP + p];
            sPt[idx] = make_float4(c.x * inv_r, c.y * inv_r, a.x, a.y);
            sBc[idx] = make_float2(kbx[rnd] + rmaxf - 0.5f,
                                   kby[rnd] + rmaxf - 0.5f);
        }
    }
    __syncthreads();

    // ---- per-pixel accumulation: 4 rows per thread ----
    const float pxf  = (float)(x0 + lane);
    const float pyf0 = (float)(y0 + wid);
    const float pxs  = pxf * inv_r;
    const float pys0 = pyf0 * inv_r;
    const float d4s  = 4.0f * inv_r;
    const float hw   = rmaxf - 0.5f;

    float ax0 = 0.f, ay0 = 0.f, ax1 = 0.f, ay1 = 0.f;
    float ax2 = 0.f, ay2 = 0.f, ax3 = 0.f, ay3 = 0.f;

#pragma unroll 2
    for (int k = 0; k < K; ++k) {
        const float4 P  = sPt[k];
        const float2 Bc = sBc[k];
        const float dxs = pxs - P.x;
        const float dx2 = dxs * dxs;
        const bool  inx = fabsf(pxf - Bc.x) <= hw;    // hoisted x predicate
        float dys = pys0 - P.y;
        float dyb = pyf0 - Bc.y;

#define ROW(AX, AY)                                                          \
        {                                                                    \
            const float d2 = fmaf(dys, dys, dx2);                            \
            float dist;                                                      \
            asm("sqrt.approx.f32 %0, %1;" : "=f"(dist) : "f"(d2));           \
            const float om  = __saturatef(1.0f - dist);                      \
            const float om2 = om * om;                                       \
            const float w   = (om2 * om2) * fmaf(4.0f, dist, 1.0f);          \
            if (inx & (fabsf(dyb) <= hw)) {                                  \
                AX = fmaf(w, P.z, AX);                                       \
                AY = fmaf(w, P.w, AY);                                       \
            }                                                                \
            dys += d4s;                                                      \
            dyb += 4.0f;                                                     \
        }
        ROW(ax0, ay0) ROW(ax1, ay1) ROW(ax2, ay2) ROW(ax3, ay3)
#undef ROW
    }

    // ---- write out (coalesced per warp) ----
    float* __restrict__ o0 = out + (size_t)b * 2 * PLANE;
    const int p0 = (y0 + wid) * IMG + x0 + lane;
    o0[p0]                 = ax0;  o0[p0 + PLANE]             = ay0;
    o0[p0 + 4 * IMG]       = ax1;  o0[p0 + 4 * IMG + PLANE]   = ay1;
    o0[p0 + 8 * IMG]       = ax2;  o0[p0 + 8 * IMG + PLANE]   = ay2;
    o0[p0 + 12 * IMG]      = ax3;  o0[p0 + 12 * IMG + PLANE]  = ay3;
}

// ---------------------------------------------------------------------------
extern "C" void kernel_launch(void* const* d_in, const int* in_sizes, int n_in,
                              void* d_out, int out_size) {
    const float* cpoint = (const float*)d_in[0];  // [4,512,2]
    const float* alpha  = (const float*)d_in[1];  // [4,512,2]
    float* out = (float*)d_out;                   // [4,2,512,512]
    (void)in_sizes; (void)n_in; (void)out_size;

    nn_kernel<<<32, 512>>>(cpoint);
    gather_kernel<<<NB * 512, TPB>>>(cpoint, alpha, out);
}

// round 8
// speedup vs baseline: 2.1378x; 1.1620x over previous
#include <cuda_runtime.h>
#include <math.h>

#define IMG   512
#define NB    4
#define NP    512
#define RCAP  37
#define PLANE (IMG * IMG)
#define TW    32
#define TH    16
#define TPB   128
#define GRID  2048          // == NB * 512 tiles; all resident (16 blocks/SM * 148)

// 32 NN partials: g_part[batch*8 + seg] = max over 64 points of min-NN d^2
__device__ float g_part[32];
// epoch grid barrier: grows by GRID per launch/replay
__device__ unsigned int g_bar;

__global__ void __launch_bounds__(TPB, 16)
fused_kernel(const float* __restrict__ cp,
             const float* __restrict__ alpha,
             float* __restrict__ out)
{
    const int blk  = blockIdx.x;
    const int t    = threadIdx.x;
    const int lane = t & 31;
    const int wid  = t >> 5;                 // 0..3

    __shared__ float4 sPt[NP];               // gather: cx/r, cy/r, ax, ay (8KB)
    __shared__ float2 sBc[NP];               // gather: box centers (4KB)
    __shared__ float  s_invr, s_rmaxf;
    __shared__ int    s_cnt[16], s_base[16];

    // ================= phase 1: NN partials (blocks 0..31) ===================
    if (blk < 32) {
        float2* pts = (float2*)sPt;          // reuse 4KB of sPt
        float*  red = (float*)sBc;           // 4 floats
        const int batch = blk >> 3;
        const int seg   = blk & 7;

        const float2* src = (const float2*)cp + batch * NP;
        pts[t]       = src[t];
        pts[t + 128] = src[t + 128];
        pts[t + 256] = src[t + 256];
        pts[t + 384] = src[t + 384];
        __syncthreads();

        const int i   = seg * 64 + (t >> 1); // 2 threads per point
        const int sub = t & 1;               // each scans 256 j's
        const float2 me = pts[i];

        float mind2 = 3.0e38f;
        const int j0 = sub * 256;
#pragma unroll 8
        for (int j = j0; j < j0 + 256; ++j) {
            float dx = me.x - pts[j].x;
            float dy = me.y - pts[j].y;
            float d2 = fmaf(dy, dy, dx * dx);
            if (j != i) mind2 = fminf(mind2, d2);
        }
        mind2 = fminf(mind2, __shfl_down_sync(0xffffffffu, mind2, 1, 2));
        // lanes with sub==0 hold the per-point min; others contribute 0 to max
        float v = (sub == 0) ? mind2 : 0.0f;
#pragma unroll
        for (int o = 16; o > 0; o >>= 1)
            v = fmaxf(v, __shfl_xor_sync(0xffffffffu, v, o));
        if (lane == 0) red[wid] = v;
        __syncthreads();
        if (t == 0) {
            g_part[blk] = fmaxf(fmaxf(red[0], red[1]), fmaxf(red[2], red[3]));
            __threadfence();
        }
    }

    // ================= grid barrier (replay-safe epoch) ======================
    if (t == 0) {
        __threadfence();
        const unsigned base   = atomicAdd(&g_bar, 1u);
        const unsigned target = (base / GRID + 1u) * GRID;
        while (*((volatile unsigned*)&g_bar) < target) { }
        __threadfence();
    }
    __syncthreads();

    // ================= phase 2: gather (all 2048 blocks) =====================
    const int b    = blk >> 9;               // 512 tiles per batch
    const int tile = blk & 511;
    const int x0   = (tile & 15) << 5;
    const int y0   = (tile >> 4) << 4;

    // fold the 32 NN partials (warp 0)
    if (t < 32) {
        float v = g_part[t];
        float g8 = v;
        g8 = fmaxf(g8, __shfl_xor_sync(0xffffffffu, g8, 4));
        g8 = fmaxf(g8, __shfl_xor_sync(0xffffffffu, g8, 2));
        g8 = fmaxf(g8, __shfl_xor_sync(0xffffffffu, g8, 1));
        float ga = g8;
        ga = fmaxf(ga, __shfl_xor_sync(0xffffffffu, ga, 8));
        ga = fmaxf(ga, __shfl_xor_sync(0xffffffffu, ga, 16));
        const float own = __shfl_sync(0xffffffffu, g8, b * 8);
        if (t == 0) {
            const float r    = 2.0f * sqrtf(own);
            const float rall = 2.0f * sqrtf(ga);
            s_rmaxf = fminf(ceilf(rall), (float)RCAP);
            s_invr  = 1.0f / r;
        }
    }
    __syncthreads();

    const float rmaxf = s_rmaxf;
    const float inv_r = s_invr;
    const float lo = rmaxf, hi = (float)IMG - rmaxf;
    const float W2m1 = 2.0f * rmaxf - 1.0f;
    const float xlo = (float)x0 - W2m1, xhi = (float)(x0 + TW - 1);
    const float ylo = (float)y0 - W2m1, yhi = (float)(y0 + TH - 1);

    // prefilter all 4 rounds, then one prefix + one scatter
    bool     keep[4];
    unsigned msk[4];
    float    kbx[4], kby[4];
#pragma unroll
    for (int rnd = 0; rnd < 4; ++rnd) {
        const int p = t + rnd * TPB;
        const float2 c = ((const float2*)cp)[b * NP + p];
        const float bx = floorf(fminf(fmaxf(c.x, lo), hi)) - rmaxf;
        const float by = floorf(fminf(fmaxf(c.y, lo), hi)) - rmaxf;
        keep[rnd] = (bx >= xlo) & (bx <= xhi) & (by >= ylo) & (by <= yhi);
        kbx[rnd] = bx; kby[rnd] = by;
        msk[rnd] = __ballot_sync(0xffffffffu, keep[rnd]);
        if (lane == 0) s_cnt[rnd * 4 + wid] = __popc(msk[rnd]);
    }
    __syncthreads();
    if (t == 0) {
        int run = 0;
#pragma unroll
        for (int i = 0; i < 16; ++i) { s_base[i] = run; run += s_cnt[i]; }
        s_cnt[0] = run;
    }
    __syncthreads();
    const int K = s_cnt[0];
#pragma unroll
    for (int rnd = 0; rnd < 4; ++rnd) {
        if (keep[rnd]) {
            const int p   = t + rnd * TPB;
            const int idx = s_base[rnd * 4 + wid] +
                            __popc(msk[rnd] & ((1u << lane) - 1u));
            const float2 c = ((const float2*)cp)[b * NP + p];
            const float2 a = ((const float2*)alpha)[b * NP + p];
            sPt[idx] = make_float4(c.x * inv_r, c.y * inv_r, a.x, a.y);
            sBc[idx] = make_float2(kbx[rnd] + rmaxf - 0.5f,
                                   kby[rnd] + rmaxf - 0.5f);
        }
    }
    __syncthreads();

    // per-pixel accumulation: 4 rows per thread
    const float pxf  = (float)(x0 + lane);
    const float pyf0 = (float)(y0 + wid);
    const float pxs  = pxf * inv_r;
    const float pys0 = pyf0 * inv_r;
    const float d4s  = 4.0f * inv_r;
    const float hw   = rmaxf - 0.5f;

    float ax0 = 0.f, ay0 = 0.f, ax1 = 0.f, ay1 = 0.f;
    float ax2 = 0.f, ay2 = 0.f, ax3 = 0.f, ay3 = 0.f;

#pragma unroll 2
    for (int k = 0; k < K; ++k) {
        const float4 P  = sPt[k];
        const float2 Bc = sBc[k];
        const float dxs = pxs - P.x;
        const float dx2 = dxs * dxs;
        const bool  inx = fabsf(pxf - Bc.x) <= hw;
        float dys = pys0 - P.y;
        float dyb = pyf0 - Bc.y;

#define ROW(AX, AY)                                                          \
        {                                                                    \
            const float d2 = fmaf(dys, dys, dx2);                            \
            float dist;                                                      \
            asm("sqrt.approx.f32 %0, %1;" : "=f"(dist) : "f"(d2));           \
            const float om  = __saturatef(1.0f - dist);                      \
            const float om2 = om * om;                                       \
            const float w   = (om2 * om2) * fmaf(4.0f, dist, 1.0f);          \
            if (inx & (fabsf(dyb) <= hw)) {                                  \
                AX = fmaf(w, P.z, AX);                                       \
                AY = fmaf(w, P.w, AY);                                       \
            }                                                                \
            dys += d4s;                                                      \
            dyb += 4.0f;                                                     \
        }
        ROW(ax0, ay0) ROW(ax1, ay1) ROW(ax2, ay2) ROW(ax3, ay3)
#undef ROW
    }

    // write out (coalesced per warp)
    float* __restrict__ o0 = out + (size_t)b * 2 * PLANE;
    const int p0 = (y0 + wid) * IMG + x0 + lane;
    o0[p0]                 = ax0;  o0[p0 + PLANE]             = ay0;
    o0[p0 + 4 * IMG]       = ax1;  o0[p0 + 4 * IMG + PLANE]   = ay1;
    o0[p0 + 8 * IMG]       = ax2;  o0[p0 + 8 * IMG + PLANE]   = ay2;
    o0[p0 + 12 * IMG]      = ax3;  o0[p0 + 12 * IMG + PLANE]  = ay3;
}

// ---------------------------------------------------------------------------
extern "C" void kernel_launch(void* const* d_in, const int* in_sizes, int n_in,
                              void* d_out, int out_size) {
    const float* cpoint = (const float*)d_in[0];  // [4,512,2]
    const float* alpha  = (const float*)d_in[1];  // [4,512,2]
    float* out = (float*)d_out;                   // [4,2,512,512]
    (void)in_sizes; (void)n_in; (void)out_size;

    fused_kernel<<<GRID, TPB>>>(cpoint, alpha, out);
}